// round 3
// baseline (speedup 1.0000x reference)
#include <cuda_runtime.h>

// Fused cosine-score attention, single query.
// stage1: single streaming pass over keys (128 MB). Warp-per-row, packed
//   f32x2 FMA math (Blackwell FFMA2 via PTX), register-resident 1024-float
//   accumulator, block smem tree reduce -> 148 block partials (606 KB).
// stage2: 128-block parallel reduction of the partials.

#define NBLK 148
#define NTHR 512
#define WPB  (NTHR / 32)           // 16 warps per block
#define NWARPS (NBLK * WPB)        // 2368
#define H 1024
#define HV4 (H / 4)

typedef unsigned long long u64;

__device__ float4 g_partial[NBLK][HV4];   // 606 KB scratch

__device__ __forceinline__ u64 ffma2(u64 a, u64 b, u64 c) {
    u64 d;
    asm("fma.rn.f32x2 %0, %1, %2, %3;" : "=l"(d) : "l"(a), "l"(b), "l"(c));
    return d;
}
__device__ __forceinline__ u64 pack2(float x, float y) {
    u64 d;
    asm("mov.b64 %0, {%1, %2};" : "=l"(d) : "f"(x), "f"(y));
    return d;
}
__device__ __forceinline__ float2 unpack2(u64 v) {
    float2 r;
    asm("mov.b64 {%0, %1}, %2;" : "=f"(r.x), "=f"(r.y) : "l"(v));
    return r;
}

__global__ __launch_bounds__(NTHR, 1)
void bahdanau_stage1(const float* __restrict__ q,
                     const float* __restrict__ keys, int S) {
    const int wib  = threadIdx.x >> 5;
    const int warp = blockIdx.x * WPB + wib;
    const int lane = threadIdx.x & 31;

    __shared__ float4 red[8][HV4];   // 32 KB, reused across reduction phases

    // q slice for this lane (as packed pairs) + |q|
    const ulonglong2* q2 = (const ulonglong2*)q;
    ulonglong2 qv[8];
    float qss;
    {
        u64 qs = 0;
#pragma unroll
        for (int i = 0; i < 8; i++) {
            qv[i] = q2[i * 32 + lane];
            qs = ffma2(qv[i].x, qv[i].x, qs);
            qs = ffma2(qv[i].y, qv[i].y, qs);
        }
        float2 t = unpack2(qs);
        qss = t.x + t.y;
    }
#pragma unroll
    for (int o = 16; o; o >>= 1) qss += __shfl_xor_sync(0xffffffffu, qss, o);
    const float inv_qn = rsqrtf(qss);

    ulonglong2 acc[8];
#pragma unroll
    for (int i = 0; i < 8; i++) { acc[i].x = 0; acc[i].y = 0; }

    for (int s = warp; s < S; s += NWARPS) {
        const ulonglong2* row = (const ulonglong2*)(keys + (size_t)s * H);
        ulonglong2 kv[8];
        u64 dp = 0, kp = 0;
#pragma unroll
        for (int i = 0; i < 8; i++) {
            kv[i] = row[i * 32 + lane];
            dp = ffma2(kv[i].x, qv[i].x, dp);
            dp = ffma2(kv[i].y, qv[i].y, dp);
            kp = ffma2(kv[i].x, kv[i].x, kp);
            kp = ffma2(kv[i].y, kv[i].y, kp);
        }
        float2 dt = unpack2(dp);
        float2 kt = unpack2(kp);
        float dot = dt.x + dt.y;
        float kss = kt.x + kt.y;
#pragma unroll
        for (int o = 16; o; o >>= 1) {
            dot += __shfl_xor_sync(0xffffffffu, dot, o);
            kss += __shfl_xor_sync(0xffffffffu, kss, o);
        }
        const float score = dot * inv_qn * rsqrtf(kss);
        const u64 s2 = pack2(score, score);
#pragma unroll
        for (int i = 0; i < 8; i++) {
            acc[i].x = ffma2(s2, kv[i].x, acc[i].x);
            acc[i].y = ffma2(s2, kv[i].y, acc[i].y);
        }
    }

    // Block tree reduction: 16 -> 8 -> 4 -> 2 -> 1 warps.
#pragma unroll
    for (int half = 8; half >= 1; half >>= 1) {
        if (wib >= half && wib < 2 * half) {
            float4* dst = (float4*)&red[wib - half][0];
#pragma unroll
            for (int i = 0; i < 8; i++)
                *(ulonglong2*)&dst[i * 32 + lane] = acc[i];
        }
        __syncthreads();
        if (wib < half) {
            const ulonglong2* src = (const ulonglong2*)&red[wib][0];
#pragma unroll
            for (int i = 0; i < 8; i++) {
                ulonglong2 v = src[i * 32 + lane];
                // unpack-free add via f32x2: acc += v  (fma with 1.0x2)
                const u64 one2 = 0x3f8000003f800000ull;
                acc[i].x = ffma2(v.x, one2, acc[i].x);
                acc[i].y = ffma2(v.y, one2, acc[i].y);
            }
        }
        __syncthreads();
    }

    if (wib == 0) {
#pragma unroll
        for (int i = 0; i < 8; i++)
            *(ulonglong2*)&g_partial[blockIdx.x][i * 32 + lane] = acc[i];
    }
}

// stage2: out[h] = sum_{b<148} g_partial[b][h].
// 128 blocks x 256 threads; block owns 8 columns, 32 row-groups per column.
__global__ __launch_bounds__(256)
void bahdanau_stage2(float* __restrict__ out) {
    const int col = blockIdx.x * 8 + (threadIdx.x & 7);
    const int g   = threadIdx.x >> 3;   // 0..31
    const float* part = (const float*)g_partial;

    float s = 0.f;
#pragma unroll
    for (int b = 0; b < 5; b++) {       // 5*32 = 160 >= 148
        int p = g + b * 32;
        if (p < NBLK) s += part[(size_t)p * H + col];
    }

    __shared__ float sh[256];
    sh[threadIdx.x] = s;
    __syncthreads();
#pragma unroll
    for (int stride = 128; stride >= 8; stride >>= 1) {
        if (threadIdx.x < stride) sh[threadIdx.x] += sh[threadIdx.x + stride];
        __syncthreads();
    }
    if (threadIdx.x < 8) out[blockIdx.x * 8 + threadIdx.x] = sh[threadIdx.x];
}

extern "C" void kernel_launch(void* const* d_in, const int* in_sizes, int n_in,
                              void* d_out, int out_size) {
    const float* q    = (const float*)d_in[0];   // [1, 1024]
    const float* keys = (const float*)d_in[1];   // [S, 1024]
    const int S = in_sizes[1] / H;

    bahdanau_stage1<<<NBLK, NTHR>>>(q, keys, S);
    bahdanau_stage2<<<H / 8, 256>>>((float*)d_out);
}